// round 11
// baseline (speedup 1.0000x reference)
#include <cuda_runtime.h>
#include <math.h>

// Shape (2,3,128,128,128) fp32
#define NTOT   12582912
#define NGRP   24576          // 6*128*32 groups of 4 consecutive y-rows
#define ALPHA  0.001
#define WPB    4
#define BLOCK  (WPB * 32)
#define GRID   (NGRP / WPB)   // 6144

__device__ double       g_acc[3];
__device__ unsigned int g_ticket;

// ---------------- packed f32x2 helpers ----------------
typedef unsigned long long u64f2;
__device__ __forceinline__ u64f2 pk2(float lo, float hi) {
    u64f2 r; asm("mov.b64 %0, {%1, %2};" : "=l"(r) : "f"(lo), "f"(hi)); return r;
}
__device__ __forceinline__ void un2(u64f2 v, float& lo, float& hi) {
    asm("mov.b64 {%0, %1}, %2;" : "=f"(lo), "=f"(hi) : "l"(v));
}
__device__ __forceinline__ u64f2 add2(u64f2 a, u64f2 b) {
    u64f2 r; asm("add.rn.f32x2 %0, %1, %2;" : "=l"(r) : "l"(a), "l"(b)); return r;
}
__device__ __forceinline__ u64f2 mul2(u64f2 a, u64f2 b) {
    u64f2 r; asm("mul.rn.f32x2 %0, %1, %2;" : "=l"(r) : "l"(a), "l"(b)); return r;
}
__device__ __forceinline__ u64f2 fma2_(u64f2 a, u64f2 b, u64f2 c) {
    u64f2 r; asm("fma.rn.f32x2 %0, %1, %2, %3;" : "=l"(r) : "l"(a), "l"(b), "l"(c)); return r;
}
#define C_ONE   0x3F8000003F800000ull
#define C_NEG1  0xBF800000BF800000ull
#define C_NEG2  0xC0000000C0000000ull
#define C_QTR   0x3E8000003E800000ull
#define C_EPS   0x322BCC77322BCC77ull
__device__ __forceinline__ u64f2 sub2(u64f2 a, u64f2 b) { return fma2_(b, (u64f2)C_NEG1, a); }

__device__ __forceinline__ float4 f4sub(float4 a, float4 b) {
    return make_float4(a.x - b.x, a.y - b.y, a.z - b.z, a.w - b.w);
}
__device__ __forceinline__ float4 f4add(float4 a, float4 b) {
    return make_float4(a.x + b.x, a.y + b.y, a.z + b.z, a.w + b.w);
}

// One packed pair = 2 x-points.
__device__ __forceinline__ void point_pair(
    u64f2 uc, u64f2 ccL, u64f2 ccR,          // uc=(cc[k+1],cc[k+2]); L=(cc[k],cc[k+1]); R=(cc[k+2],cc[k+3])
    u64f2 di, u64f2 dj,                      // (ezw[k+1],ezw[k+2]), (eyw[k+1],eyw[k+2])
    u64f2 ezL, u64f2 ezR, u64f2 eyL, u64f2 eyR,  // for Dik=ezR-ezL, Djk=eyR-eyL
    u64f2 sz2, u64f2 sy2, u64f2 gxy2, u64f2 t2,
    float& ain_s, float& aout_s, float& ael_s,
    u64f2& ain2, u64f2& aout2)
{
    const u64f2 dk  = sub2(ccR, ccL);
    const u64f2 cii = fma2_(uc, (u64f2)C_NEG2, sz2);
    const u64f2 cjj = fma2_(uc, (u64f2)C_NEG2, sy2);
    const u64f2 ckk = fma2_(uc, (u64f2)C_NEG2, add2(ccL, ccR));
    const u64f2 lap = add2(add2(cii, cjj), ckk);

    const u64f2 Dik = sub2(ezR, ezL);
    const u64f2 Djk = sub2(eyR, eyL);

    const u64f2 di2 = mul2(di, di);
    const u64f2 dj2 = mul2(dj, dj);
    const u64f2 dk2 = mul2(dk, dk);
    const u64f2 S   = add2(add2(di2, dj2), dk2);     // = 4*(ci2+cj2+ck2)

    u64f2 acc = mul2(di2, cii);
    acc = fma2_(dj2, cjj, acc);
    acc = fma2_(dk2, ckk, acc);
    acc = fma2_(mul2(Dik, Djk), gxy2, acc);
    const u64f2 negacc = mul2(acc, (u64f2)C_NEG1);
    const u64f2 curv   = fma2_((u64f2)C_QTR, fma2_(S, lap, negacc), lap);

    const u64f2 ee  = fma2_((u64f2)C_QTR, S, (u64f2)C_EPS);   // eps + s
    const u64f2 oo  = fma2_((u64f2)C_QTR, S, (u64f2)C_ONE);   // 1 + s
    const u64f2 arg = mul2(ee, mul2(oo, oo));
    const u64f2 num = mul2(mul2(curv, curv), ee);

    float a0, a1, n0, n1;
    un2(arg, a0, a1); un2(num, n0, n1);
    ael_s = fmaf(n0, rsqrtf(a0), ael_s);       // curv^2*sqrt(ee)/oo
    ael_s = fmaf(n1, rsqrtf(a1), ael_s);

    // region terms (packed)
    const u64f2 tm1 = add2(t2, (u64f2)C_NEG1);
    ain2  = fma2_(uc, mul2(tm1, tm1), ain2);
    const u64f2 omu = fma2_(uc, (u64f2)C_NEG1, (u64f2)C_ONE);
    aout2 = fma2_(omu, mul2(t2, t2), aout2);
    (void)ain_s; (void)aout_s;
}

// One warp per group of 4 consecutive y-rows (fixed vol,z); lane = float4 of x.
__global__ __launch_bounds__(BLOCK) void ace_main(
    const float* __restrict__ yp, const float* __restrict__ yt,
    float* __restrict__ out)
{
    const unsigned FULL = 0xFFFFFFFFu;
    const int wid  = threadIdx.x >> 5;
    const int lane = threadIdx.x & 31;
    const int g    = blockIdx.x * WPB + wid;

    const int y0  = (g & 31) << 2;          // first of 4 output rows
    const int z   = (g >> 5) & 127;
    const int vol = g >> 12;
    const int zm_ = z > 0   ? z - 1 : 0;
    const int zq  = z < 127 ? z + 1 : 127;

    const float* U = yp + ((size_t)vol << 21);
    const float* T = yt + ((size_t)vol << 21);

    float4 cz[6], ez[6], sz[6];
    float4 tv[4];

    #define LOADLVL(l)                                                          \
    {   int yy = y0 - 1 + (l);                                                  \
        yy = yy < 0 ? 0 : (yy > 127 ? 127 : yy);                                \
        const float4 a_ = __ldg(((const float4*)(U + ((zm_ << 14) + (yy << 7)))) + lane); \
        const float4 b_ = __ldg(((const float4*)(U + ((zq  << 14) + (yy << 7)))) + lane); \
        const float4 c_ = __ldg(((const float4*)(U + ((z   << 14) + (yy << 7)))) + lane); \
        cz[l] = c_; ez[l] = f4sub(b_, a_); sz[l] = f4add(b_, a_);               \
    }
    #define LOADT(j)                                                            \
        tv[j] = __ldg(((const float4*)(T + ((z << 14) + ((y0 + (j)) << 7)))) + lane);

    LOADLVL(0) LOADLVL(1) LOADLVL(2) LOADLVL(3)
    LOADT(0)

    #define MK6(A, V)                                                  \
        float A[6];                                                    \
        A[1] = V.x; A[2] = V.y; A[3] = V.z; A[4] = V.w;                \
        {   float L_ = __shfl_up_sync(FULL, A[4], 1);                  \
            float R_ = __shfl_down_sync(FULL, A[1], 1);                \
            A[0] = (lane == 0)  ? A[1] : L_;                           \
            A[5] = (lane == 31) ? A[4] : R_; }

    float ain = 0.f, aout = 0.f, ael = 0.f;
    u64f2 ain2 = 0ull, aout2 = 0ull;

    #pragma unroll
    for (int j = 0; j < 4; j++) {
        if (j < 2) LOADLVL(j + 4)
        if (j < 3) LOADT(j + 1)

        const int l = j + 1;
        const float4 eyv  = f4sub(cz[l + 1], cz[l - 1]);   // u(y+1)-u(y-1)
        const float4 syv  = f4add(cz[l + 1], cz[l - 1]);
        const float4 gxyv = f4sub(ez[l + 1], ez[l - 1]);   // mixed z,y
        const float4 szl  = sz[l];

        MK6(cc,  cz[l])
        MK6(ezw, ez[l])
        MK6(eyw, eyv)

        // packed shifted windows
        const u64f2 cc01 = pk2(cc[0],  cc[1]),  cc12 = pk2(cc[1],  cc[2]);
        const u64f2 cc23 = pk2(cc[2],  cc[3]),  cc34 = pk2(cc[3],  cc[4]);
        const u64f2 cc45 = pk2(cc[4],  cc[5]);
        const u64f2 ez01 = pk2(ezw[0], ezw[1]), ez12 = pk2(ezw[1], ezw[2]);
        const u64f2 ez23 = pk2(ezw[2], ezw[3]), ez34 = pk2(ezw[3], ezw[4]);
        const u64f2 ez45 = pk2(ezw[4], ezw[5]);
        const u64f2 ey01 = pk2(eyw[0], eyw[1]), ey12 = pk2(eyw[1], eyw[2]);
        const u64f2 ey23 = pk2(eyw[2], eyw[3]), ey34 = pk2(eyw[3], eyw[4]);
        const u64f2 ey45 = pk2(eyw[4], eyw[5]);
        // naturally-paired operands
        const u64f2 sz01 = pk2(szl.x,  szl.y),  sz23 = pk2(szl.z,  szl.w);
        const u64f2 sy01 = pk2(syv.x,  syv.y),  sy23 = pk2(syv.z,  syv.w);
        const u64f2 gx01 = pk2(gxyv.x, gxyv.y), gx23 = pk2(gxyv.z, gxyv.w);
        const u64f2 t01  = pk2(tv[j].x, tv[j].y), t23 = pk2(tv[j].z, tv[j].w);

        // pair (k=0,1)
        point_pair(cc12, cc01, cc23, ez12, ey12,
                   ez01, ez23, ey01, ey23,
                   sz01, sy01, gx01, t01,
                   ain, aout, ael, ain2, aout2);
        // pair (k=2,3)
        point_pair(cc34, cc23, cc45, ez34, ey34,
                   ez23, ez45, ey23, ey45,
                   sz23, sy23, gx23, t23,
                   ain, aout, ael, ain2, aout2);
    }
    #undef MK6
    #undef LOADLVL
    #undef LOADT

    {   float lo, hi;
        un2(ain2, lo, hi);  ain  = lo + hi;
        un2(aout2, lo, hi); aout = lo + hi;
    }

    // ---- block reduction ----
    #pragma unroll
    for (int o = 16; o > 0; o >>= 1) {
        ain  += __shfl_down_sync(FULL, ain,  o);
        aout += __shfl_down_sync(FULL, aout, o);
        ael  += __shfl_down_sync(FULL, ael,  o);
    }
    __shared__ float si[WPB], so[WPB], se[WPB];
    if (lane == 0) { si[wid] = ain; so[wid] = aout; se[wid] = ael; }
    __syncthreads();

    if (threadIdx.x == 0) {
        float A = si[0] + si[1] + si[2] + si[3];
        float B = so[0] + so[1] + so[2] + so[3];
        float E = se[0] + se[1] + se[2] + se[3];
        atomicAdd(&g_acc[0], (double)A);
        atomicAdd(&g_acc[1], (double)B);
        atomicAdd(&g_acc[2], (double)E);
        __threadfence();
        unsigned t = atomicAdd(&g_ticket, 1u);
        if (t == (unsigned)(GRID - 1)) {          // last block finalizes + resets
            __threadfence();
            double s0 = atomicAdd(&g_acc[0], 0.0);
            double s1 = atomicAdd(&g_acc[1], 0.0);
            double s2 = atomicAdd(&g_acc[2], 0.0);
            double res = fabs(s0) + fabs(s1) + s2 + ALPHA * (double)NTOT;
            out[0] = (float)res;
            g_acc[0] = 0.0; g_acc[1] = 0.0; g_acc[2] = 0.0;
            g_ticket = 0u;
        }
    }
}

extern "C" void kernel_launch(void* const* d_in, const int* in_sizes, int n_in,
                              void* d_out, int out_size) {
    const float* y_pred = (const float*)d_in[0];
    const float* y_true = (const float*)d_in[1];
    ace_main<<<GRID, BLOCK>>>(y_pred, y_true, (float*)d_out);
}